// round 15
// baseline (speedup 1.0000x reference)
#include <cuda_runtime.h>
#include <cuda_fp16.h>
#include <stdint.h>

// Problem constants
#define B     1024
#define S     2048
#define R1    20000
#define R2    40000
#define RTOT  (R1 + R2)            // 60000 concatenated reactions
#define NPAIR (B / 2)              // 512 row-pairs

#define MAIN_THREADS 512
#define NPART 4                    // uniform partitions over the concat stream
#define RPP   15000                // reactions per partition
#define EPT   30                   // entries per thread per partition (pad 15360)
#define PART_PAD (EPT * MAIN_THREADS)   // 15360
#define SLOTS_TOT (NPART * PART_PAD)    // 61440
#define ONE_IDX 2048u              // y slot holding 1.0 (first-order rb target)
#define KPAD  2048u                // pad-entry key (discard slot)
#define SINK  2049                 // redirect target for non-closing RMWs
#define ACC_SLOTS 2052
#define Y_SLOTS 2052
#define CHUNK 5                    // EPT/CHUNK = 6 double-buffered stages

// ---------------- static device scratch (no runtime allocation) ----------------
__device__ int       g_counts[NPART][S];   // zero-init; scan re-zeroes
__device__ int       g_cur[NPART][S];
// Key-grouped, transposed entry streams. u16x4: ra | rb<<16 | k<<32 | rid<<48
// (first-order: rb = ONE_IDX; rid is the partition-local rate index)
__device__ uint64_t  g_et[NPART][PART_PAD];
// Pre-permuted rates, half2 {row0,row1}, parallel to the entry stream layout.
__device__ uint32_t  g_rperm[NPAIR][SLOTS_TOT];   // 126MB static scratch

__device__ __forceinline__ int transposeP(int pos) {
    return (pos % EPT) * MAIN_THREADS + pos / EPT;
}
__device__ __forceinline__ uint64_t pack_entry(unsigned ra, unsigned rb,
                                               unsigned k, unsigned rid) {
    return (uint64_t)ra | ((uint64_t)rb << 16) |
           ((uint64_t)k << 32) | ((uint64_t)rid << 48);
}

// ---------------- prep kernels ----------------

__global__ void hist_kernel(const int* __restrict__ inds_1p,
                            const int* __restrict__ inds_2p) {
    int g = blockIdx.x * blockDim.x + threadIdx.x;
    if (g < RTOT) {
        int part = g / RPP;
        int p = (g < R1) ? inds_1p[g] : inds_2p[g - R1];
        atomicAdd(&g_counts[part][p], 1);
    }
}

__global__ void scan_kernel() {
    __shared__ int buf[2][S];
    const int tid  = threadIdx.x;       // 1024 threads, 2 elems each
    const int part = blockIdx.x;
    int* cnt = g_counts[part];
    int* cur = g_cur[part];

    buf[0][tid]        = cnt[tid];
    buf[0][tid + 1024] = cnt[tid + 1024];
    cnt[tid]        = 0;
    cnt[tid + 1024] = 0;
    __syncthreads();

    int src = 0;
    for (int off = 1; off < S; off <<= 1) {
        int i0 = tid, i1 = tid + 1024;
        int v0 = buf[src][i0] + (i0 >= off ? buf[src][i0 - off] : 0);
        int v1 = buf[src][i1] + (i1 >= off ? buf[src][i1 - off] : 0);
        __syncthreads();
        buf[1 - src][i0] = v0;
        buf[1 - src][i1] = v1;
        __syncthreads();
        src ^= 1;
    }
    cur[tid]        = (tid == 0) ? 0 : buf[src][tid - 1];
    cur[tid + 1024] = buf[src][tid + 1023];
}

__global__ void scatter_pad_kernel(const int* __restrict__ inds_1r,
                                   const int* __restrict__ inds_1p,
                                   const int* __restrict__ inds_2r,
                                   const int* __restrict__ inds_2p) {
    int g = blockIdx.x * blockDim.x + threadIdx.x;
    if (g < RTOT) {
        int part = g / RPP;
        int rid  = g - part * RPP;
        unsigned ra, rb, p;
        if (g < R1) {
            ra = (unsigned)inds_1r[g]; rb = ONE_IDX; p = (unsigned)inds_1p[g];
        } else {
            int j = g - R1;
            ra = (unsigned)inds_2r[2 * j]; rb = (unsigned)inds_2r[2 * j + 1];
            p = (unsigned)inds_2p[j];
        }
        int pos = atomicAdd(&g_cur[part][p], 1);
        g_et[part][transposeP(pos)] = pack_entry(ra, rb, p, (unsigned)rid);
    } else if (g < RTOT + NPART * (PART_PAD - RPP)) {
        int q    = g - RTOT;
        int part = q / (PART_PAD - RPP);
        int slot = RPP + q % (PART_PAD - RPP);
        g_et[part][transposeP(slot)] = pack_entry(ONE_IDX, ONE_IDX, KPAD, 0);
    }
}

// ---------------- permute kernel ----------------
// One CTA per row-pair: stage each 15000-rate partition as half2 {row0,row1}
// in SMEM (coalesced float4 loads), then resolve the random rid lookup ONCE,
// writing rates pre-permuted into entry order (coalesced STG.32). This is
// the minimal random-LDS kernel: LDG entry -> 1 random LDS -> STG.

__global__ __launch_bounds__(MAIN_THREADS, 3)
void permute_kernel(const float* __restrict__ rates_1st,
                    const float* __restrict__ rates_2nd) {
    extern __shared__ unsigned rbuf[];   // [RPP] packed half2
    const int pair = blockIdx.x;
    const int b0 = 2 * pair, b1 = b0 + 1;
    const int tid = threadIdx.x;

    #pragma unroll 1
    for (int part = 0; part < NPART; ++part) {
        __syncthreads();
        const int gb = part * RPP;
        for (int i = tid; i < RPP / 4; i += MAIN_THREADS) {
            int g = gb + 4 * i;          // concat index; float4 never straddles R1
            const float4* s0;
            const float4* s1;
            if (g < R1) {
                s0 = (const float4*)(rates_1st + (size_t)b0 * R1 + g);
                s1 = (const float4*)(rates_1st + (size_t)b1 * R1 + g);
            } else {
                s0 = (const float4*)(rates_2nd + (size_t)b0 * R2 + (g - R1));
                s1 = (const float4*)(rates_2nd + (size_t)b1 * R2 + (g - R1));
            }
            float4 r0 = __ldcs(s0);
            float4 r1 = __ldcs(s1);
            __half2 t[4];
            t[0] = __floats2half2_rn(r0.x, r1.x);
            t[1] = __floats2half2_rn(r0.y, r1.y);
            t[2] = __floats2half2_rn(r0.z, r1.z);
            t[3] = __floats2half2_rn(r0.w, r1.w);
            *(uint4*)(rbuf + 4 * i) = *(const uint4*)t;           // STS.128
        }
        __syncthreads();

        uint32_t* dst = g_rperm[pair] + part * PART_PAD;
        const uint64_t* ep = g_et[part];
        for (int slot = tid; slot < PART_PAD; slot += MAIN_THREADS) {
            unsigned rid = (unsigned)(ep[slot] >> 48);
            dst[slot] = rbuf[rid];       // 1 random LDS.32 -> coalesced STG.32
        }
    }
}

// ---------------- main kernel ----------------
// TWO batch rows per CTA. Rates arrive pre-permuted (coalesced LDG.32 in
// lockstep with entries) -> only 2 random LDS per entry (y[ra], y[rb]), no
// rate staging, no rid decode. SMEM = y2h(8.2KB) + acc2(16.4KB) = 24.8KB.
// Close logic = proven R8 pattern: interior runs via SEL-redirected RMW
// (sink for non-closes); per-partition slice-boundary runs via spread SMEM
// atomics between barriers.

#define SMEM_BYTES (Y_SLOTS * 4 + 2 * ACC_SLOTS * 4)

__device__ __forceinline__ void sweep2(
    const uint64_t* __restrict__ ep,      // g_et[part] + tid
    const uint32_t* __restrict__ rp,      // g_rperm[pair] + part*PART_PAD + tid
    const __half2* __restrict__ y2h,
    float* __restrict__ acc2,
    unsigned& firstk, float& f0, float& f1, unsigned& fdone,
    unsigned& lastk, float& l0, float& l1)
{
    uint64_t ebuf0[CHUNK], ebuf1[CHUNK];
    uint32_t rbuf0[CHUNK], rbuf1[CHUNK];
    #pragma unroll
    for (int u = 0; u < CHUNK; ++u) {
        ebuf0[u] = ep[u * MAIN_THREADS];
        rbuf0[u] = rp[u * MAIN_THREADS];
    }

    unsigned curk = 0;
    float a0 = 0.f, a1 = 0.f;
    unsigned first_done = 0;
    firstk = SINK; f0 = 0.f; f1 = 0.f;

    #pragma unroll
    for (int c = 0; c < EPT / CHUNK; ++c) {
        uint64_t* ecur = (c & 1) ? ebuf1 : ebuf0;
        uint64_t* enxt = (c & 1) ? ebuf0 : ebuf1;
        uint32_t* rcur = (c & 1) ? rbuf1 : rbuf0;
        uint32_t* rnxt = (c & 1) ? rbuf0 : rbuf1;
        if (c + 1 < EPT / CHUNK) {
            const uint64_t* np = ep + (c + 1) * CHUNK * MAIN_THREADS;
            const uint32_t* nr = rp + (c + 1) * CHUNK * MAIN_THREADS;
            #pragma unroll
            for (int u = 0; u < CHUNK; ++u) {
                enxt[u] = np[u * MAIN_THREADS];
                rnxt[u] = nr[u * MAIN_THREADS];
            }
        }
        #pragma unroll
        for (int u = 0; u < CHUNK; ++u) {
            uint64_t e  = ecur[u];
            unsigned lo = (unsigned)e;
            unsigned hi = (unsigned)(e >> 32);
            unsigned ra = lo & 0xFFFFu;
            unsigned rb = lo >> 16;
            unsigned k  = hi & 0xFFFFu;
            float2 fa = __half22float2(y2h[ra]);     // random LDS.32
            float2 fb = __half22float2(y2h[rb]);     // random or broadcast
            __half2 hr; *(uint32_t*)&hr = rcur[u];   // rate from register
            float2 fr = __half22float2(hr);
            float v0 = fa.x * fb.x * fr.x;
            float v1 = fa.y * fb.y * fr.y;
            if (c == 0 && u == 0) {
                curk = k; a0 = v0; a1 = v1;          // prime first run
            } else {
                unsigned diff     = (k != curk) ? 1u : 0u;
                unsigned do_store = diff & first_done;
                float* addr = do_store ? (acc2 + 2 * curk) : (acc2 + 2 * SINK);
                float2 t = *(float2*)addr;           // unconditional LDS.64
                t.x += a0; t.y += a1;
                *(float2*)addr = t;                  // unconditional STS.64
                unsigned cap = diff & (1u - first_done);
                firstk = cap ? curk : firstk;
                f0     = cap ? a0   : f0;
                f1     = cap ? a1   : f1;
                first_done |= diff;
                a0 = diff ? v0 : (a0 + v0);
                a1 = diff ? v1 : (a1 + v1);
                curk = k;
            }
        }
    }
    fdone = first_done;
    lastk = curk; l0 = a0; l1 = a1;
}

__global__ __launch_bounds__(MAIN_THREADS, 2)
void reaction_main_kernel(const float* __restrict__ y_in,
                          float* __restrict__ y_out) {
    extern __shared__ char smraw[];
    __half2* y2h  = (__half2*)smraw;                  // [Y_SLOTS]
    float*   acc2 = (float*)(smraw + Y_SLOTS * 4);    // [2*ACC_SLOTS]

    const int pair = blockIdx.x;
    const int b0 = 2 * pair, b1 = b0 + 1;
    const int tid = threadIdx.x;

    // Load two y rows -> packed half2; ONE slot; zero accumulator.
    {
        const float4* s0 = (const float4*)(y_in + (size_t)b0 * S);
        const float4* s1 = (const float4*)(y_in + (size_t)b1 * S);
        float4 r0 = s0[tid], r1 = s1[tid];
        __half2 t[4];
        t[0] = __floats2half2_rn(r0.x, r1.x);
        t[1] = __floats2half2_rn(r0.y, r1.y);
        t[2] = __floats2half2_rn(r0.z, r1.z);
        t[3] = __floats2half2_rn(r0.w, r1.w);
        *(uint4*)(y2h + 4 * tid) = *(const uint4*)t;  // STS.128
        if (tid == 0)
            y2h[ONE_IDX] = __floats2half2_rn(1.f, 1.f);
        #pragma unroll
        for (int i = tid; i < 2 * ACC_SLOTS; i += MAIN_THREADS)
            acc2[i] = 0.f;
    }
    __syncthreads();

    #pragma unroll 1
    for (int part = 0; part < NPART; ++part) {
        unsigned firstk, fdone, lastk;
        float f0, f1, l0, l1;
        sweep2(g_et[part] + tid,
               g_rperm[pair] + part * PART_PAD + tid,
               y2h, acc2,
               firstk, f0, f1, fdone, lastk, l0, l1);

        __syncthreads();   // interior RMWs visible before boundary atomics
        atomicAdd(&acc2[2 * lastk],     l0);
        atomicAdd(&acc2[2 * lastk + 1], l1);
        if (fdone) {
            atomicAdd(&acc2[2 * firstk],     f0);
            atomicAdd(&acc2[2 * firstk + 1], f1);
        }
        __syncthreads();   // atomics done before next partition's RMWs
    }

    // ---- write out both rows ----
    #pragma unroll
    for (int i = tid; i < S; i += MAIN_THREADS) {
        float2 t = *(const float2*)(acc2 + 2 * i);
        y_out[(size_t)b0 * S + i] = t.x;
        y_out[(size_t)b1 * S + i] = t.y;
    }
}

// ---------------- launch ----------------

extern "C" void kernel_launch(void* const* d_in, const int* in_sizes, int n_in,
                              void* d_out, int out_size) {
    const float* y_in      = (const float*)d_in[0];
    const float* rates_1st = (const float*)d_in[1];
    const float* rates_2nd = (const float*)d_in[2];
    const int*   inds_1r   = (const int*)d_in[3];
    const int*   inds_1p   = (const int*)d_in[4];
    const int*   inds_2r   = (const int*)d_in[5];
    const int*   inds_2p   = (const int*)d_in[6];
    float*       y_out     = (float*)d_out;

    cudaFuncSetAttribute(permute_kernel,
                         cudaFuncAttributeMaxDynamicSharedMemorySize,
                         RPP * (int)sizeof(unsigned));
    cudaFuncSetAttribute(reaction_main_kernel,
                         cudaFuncAttributeMaxDynamicSharedMemorySize,
                         SMEM_BYTES);

    // Entry-stream build (rebuilt every launch; deterministic).
    hist_kernel<<<(RTOT + 255) / 256, 256>>>(inds_1p, inds_2p);
    scan_kernel<<<NPART, 1024>>>();
    int scat_n = RTOT + NPART * (PART_PAD - RPP);
    scatter_pad_kernel<<<(scat_n + 255) / 256, 256>>>(inds_1r, inds_1p, inds_2r, inds_2p);

    // Resolve the random rate lookup once, writing rates in entry order.
    permute_kernel<<<NPAIR, MAIN_THREADS, RPP * sizeof(unsigned)>>>(
        rates_1st, rates_2nd);

    // Main pass: one CTA per TWO batch rows, rates streamed coalesced.
    reaction_main_kernel<<<NPAIR, MAIN_THREADS, SMEM_BYTES>>>(y_in, y_out);
}

// round 16
// speedup vs baseline: 1.6164x; 1.6164x over previous
#include <cuda_runtime.h>
#include <cuda_fp16.h>
#include <stdint.h>

// Problem constants
#define B     1024
#define S     2048
#define R1    20000
#define R2    40000
#define RTOT  (R1 + R2)            // 60000 concatenated reactions
#define NPAIR (B / 2)

#define MAIN_THREADS 512
#define NPART 12                   // partitions over the concat stream
#define RPP   5120                 // reactions per partition (NPART*RPP = 61440)
#define EPT   10                   // entries per thread per partition
#define PART_PAD (EPT * MAIN_THREADS)   // 5120 == RPP (only part 11 has pads)
#define ONE_IDX 2048u              // y slot holding 1.0 (first-order rb target)
#define KPAD  2048u                // pad-entry key (discard slot; > all real keys)
#define SINK  2049                 // redirect target for non-closing RMWs
#define ACC_SLOTS 2052
#define Y_SLOTS 2052
#define STG_F2 5                   // float2 loads per row per thread per partition

// ---------------- static device scratch (no runtime allocation) ----------------
__device__ int       g_counts[NPART][S];   // zero-init; scan re-zeroes
__device__ int       g_cur[NPART][S];
// Key-grouped, transposed entry streams. u16x4: ra | rb<<16 | k<<32 | rid<<48
// (first-order: rb = ONE_IDX; rid is the partition-local rate index < 5120)
__device__ uint64_t  g_et[NPART][PART_PAD];

__device__ __forceinline__ int transposeP(int pos) {
    return (pos % EPT) * MAIN_THREADS + pos / EPT;
}
__device__ __forceinline__ uint64_t pack_entry(unsigned ra, unsigned rb,
                                               unsigned k, unsigned rid) {
    return (uint64_t)ra | ((uint64_t)rb << 16) |
           ((uint64_t)k << 32) | ((uint64_t)rid << 48);
}

// ---------------- prep kernels ----------------

__global__ void hist_kernel(const int* __restrict__ inds_1p,
                            const int* __restrict__ inds_2p) {
    int g = blockIdx.x * blockDim.x + threadIdx.x;
    if (g < RTOT) {
        int part = g / RPP;
        int p = (g < R1) ? inds_1p[g] : inds_2p[g - R1];
        atomicAdd(&g_counts[part][p], 1);
    }
}

// One CTA per partition: exclusive scan over its 2048 bins -> running cursors.
__global__ void scan_kernel() {
    __shared__ int buf[2][S];
    const int tid  = threadIdx.x;       // 1024 threads, 2 elems each
    const int part = blockIdx.x;
    int* cnt = g_counts[part];
    int* cur = g_cur[part];

    buf[0][tid]        = cnt[tid];
    buf[0][tid + 1024] = cnt[tid + 1024];
    cnt[tid]        = 0;                 // restore zero invariant
    cnt[tid + 1024] = 0;
    __syncthreads();

    int src = 0;
    for (int off = 1; off < S; off <<= 1) {
        int i0 = tid, i1 = tid + 1024;
        int v0 = buf[src][i0] + (i0 >= off ? buf[src][i0 - off] : 0);
        int v1 = buf[src][i1] + (i1 >= off ? buf[src][i1 - off] : 0);
        __syncthreads();
        buf[1 - src][i0] = v0;
        buf[1 - src][i1] = v1;
        __syncthreads();
        src ^= 1;
    }
    cur[tid]        = (tid == 0) ? 0 : buf[src][tid - 1];
    cur[tid + 1024] = buf[src][tid + 1023];
}

// Scatter entries into key-grouped transposed slots; pads (part 11 only,
// key KPAD > all real keys so sortedness holds) fill the tail slots.
__global__ void scatter_pad_kernel(const int* __restrict__ inds_1r,
                                   const int* __restrict__ inds_1p,
                                   const int* __restrict__ inds_2r,
                                   const int* __restrict__ inds_2p) {
    int g = blockIdx.x * blockDim.x + threadIdx.x;
    if (g < RTOT) {
        int part = g / RPP;
        int rid  = g - part * RPP;
        unsigned ra, rb, p;
        if (g < R1) {
            ra = (unsigned)inds_1r[g]; rb = ONE_IDX; p = (unsigned)inds_1p[g];
        } else {
            int j = g - R1;
            ra = (unsigned)inds_2r[2 * j]; rb = (unsigned)inds_2r[2 * j + 1];
            p = (unsigned)inds_2p[j];
        }
        int pos = atomicAdd(&g_cur[part][p], 1);
        g_et[part][transposeP(pos)] = pack_entry(ra, rb, p, (unsigned)rid);
    } else if (g < NPART * RPP) {
        // pads: part = 11, slot = g - 11*RPP (real entries fill 0..3679)
        int part = g / RPP;
        int slot = g - part * RPP;
        g_et[part][transposeP(slot)] = pack_entry(ONE_IDX, ONE_IDX, KPAD, 0);
    }
}

// ---------------- main kernel ----------------
// TWO batch rows per CTA; y & rates packed __half2 {row0,row1}; fp32 register
// run accumulation with SEL-redirected interior RMW closes (sink for
// non-closes) + per-partition boundary atomics (provably disjoint addresses
// from interior RMWs -> no barrier between sweep and atomics).
//
// SOFTWARE PIPELINE: 12 partitions, two SMEM rate buffers. Per partition:
//   issue next partition's rate LDGs (registers, guarded)   <- overlaps v
//   sweep current partition (LDS-bound, hides the LDG latency)
//   convert + STS into the other buffer
//   boundary atomics; ONE __syncthreads()
// Staging DRAM traffic and sweep crossbar traffic now overlap instead of
// alternating (R8 exposed ~35us of serial staging).
//
// SMEM: y2h(8.2KB) + acc2(16.4KB) + rbuf[2](40.9KB) = 65.6KB.

#define SMEM_BYTES (Y_SLOTS * 4 + 2 * ACC_SLOTS * 4 + 2 * RPP * 4)

__global__ __launch_bounds__(MAIN_THREADS, 2)
void reaction_main_kernel(const float* __restrict__ y_in,
                          const float* __restrict__ rates_1st,
                          const float* __restrict__ rates_2nd,
                          float* __restrict__ y_out) {
    extern __shared__ char smraw[];
    __half2* y2h  = (__half2*)smraw;                           // [Y_SLOTS]
    float*   acc2 = (float*)(smraw + Y_SLOTS * 4);             // [2*ACC_SLOTS]
    __half2* rbuf = (__half2*)(smraw + Y_SLOTS * 4 + 2 * ACC_SLOTS * 4); // [2][RPP]

    const int pair = blockIdx.x;
    const int b0 = 2 * pair, b1 = b0 + 1;
    const int tid = threadIdx.x;

    const float* r0_1 = rates_1st + (size_t)b0 * R1;
    const float* r1_1 = rates_1st + (size_t)b1 * R1;
    const float* r0_2 = rates_2nd + (size_t)b0 * R2;
    const float* r1_2 = rates_2nd + (size_t)b1 * R2;

    // Load two y rows -> packed half2; ONE slot; zero accumulator.
    {
        const float4* s0 = (const float4*)(y_in + (size_t)b0 * S);
        const float4* s1 = (const float4*)(y_in + (size_t)b1 * S);
        float4 q0 = s0[tid], q1 = s1[tid];
        __half2 t[4];
        t[0] = __floats2half2_rn(q0.x, q1.x);
        t[1] = __floats2half2_rn(q0.y, q1.y);
        t[2] = __floats2half2_rn(q0.z, q1.z);
        t[3] = __floats2half2_rn(q0.w, q1.w);
        *(uint4*)(y2h + 4 * tid) = *(const uint4*)t;           // STS.128
        if (tid == 0)
            y2h[ONE_IDX] = __floats2half2_rn(1.f, 1.f);
        #pragma unroll
        for (int i = tid; i < 2 * ACC_SLOTS; i += MAIN_THREADS)
            acc2[i] = 0.f;
    }

    // ---- prologue: stage partition 0 into rbuf[0] ----
    {
        #pragma unroll
        for (int j = 0; j < STG_F2; ++j) {
            int f2 = j * MAIN_THREADS + tid;
            int g  = 2 * f2;                     // partition 0: gb = 0 (< R1)
            float2 a = *(const float2*)(r0_1 + g);
            float2 b = *(const float2*)(r1_1 + g);
            uint2 tt;
            tt.x = *(uint32_t*)&(__half2&)*(__half2[]){__floats2half2_rn(a.x, b.x)};
            (void)tt;
            __half2 ha = __floats2half2_rn(a.x, b.x);
            __half2 hb = __floats2half2_rn(a.y, b.y);
            uint2 w; w.x = *(uint32_t*)&ha; w.y = *(uint32_t*)&hb;
            *(uint2*)(rbuf + 2 * f2) = w;        // STS.64
        }
    }
    __syncthreads();

    #pragma unroll 1
    for (int p = 0; p < NPART; ++p) {
        __half2* rcur = rbuf + (p & 1) * RPP;
        __half2* rnxt = rbuf + ((p + 1) & 1) * RPP;
        const bool have = (p + 1 < NPART);

        // ---- issue next partition's rate loads (registers, guarded) ----
        float2 s0v[STG_F2], s1v[STG_F2];
        if (have) {
            const int gb = (p + 1) * RPP;
            #pragma unroll
            for (int j = 0; j < STG_F2; ++j) {
                int f2 = j * MAIN_THREADS + tid;
                int g  = gb + 2 * f2;
                float2 a = make_float2(0.f, 0.f);
                float2 b = make_float2(0.f, 0.f);
                if (g < R1) {
                    a = *(const float2*)(r0_1 + g);
                    b = *(const float2*)(r1_1 + g);
                } else if (g < RTOT) {
                    a = *(const float2*)(r0_2 + (g - R1));
                    b = *(const float2*)(r1_2 + (g - R1));
                }
                s0v[j] = a; s1v[j] = b;
            }
        }

        // ---- sweep partition p (hides the LDGs above) ----
        {
            const uint64_t* ep = &g_et[p][tid];
            uint64_t ebuf[EPT];
            #pragma unroll
            for (int u = 0; u < EPT; ++u)
                ebuf[u] = ep[u * MAIN_THREADS];   // 10 independent LDG.64

            unsigned curk = 0, first_done = 0, firstk = SINK;
            float a0 = 0.f, a1 = 0.f, f0 = 0.f, f1 = 0.f;

            #pragma unroll
            for (int u = 0; u < EPT; ++u) {
                uint64_t e  = ebuf[u];
                unsigned lo = (unsigned)e;
                unsigned hi = (unsigned)(e >> 32);
                unsigned ra  = lo & 0xFFFFu;
                unsigned rb  = lo >> 16;
                unsigned k   = hi & 0xFFFFu;
                unsigned rid = hi >> 16;
                float2 fa = __half22float2(y2h[ra]);     // random LDS.32
                float2 fb = __half22float2(y2h[rb]);     // random or broadcast
                float2 fr = __half22float2(rcur[rid]);   // random LDS.32
                float v0 = fa.x * fb.x * fr.x;
                float v1 = fa.y * fb.y * fr.y;
                if (u == 0) {
                    curk = k; a0 = v0; a1 = v1;          // prime first run
                } else {
                    unsigned diff     = (k != curk) ? 1u : 0u;
                    unsigned do_store = diff & first_done;
                    float* addr = do_store ? (acc2 + 2 * curk) : (acc2 + 2 * SINK);
                    float2 t = *(float2*)addr;           // unconditional LDS.64
                    t.x += a0; t.y += a1;
                    *(float2*)addr = t;                  // unconditional STS.64
                    unsigned cap = diff & (1u - first_done);
                    firstk = cap ? curk : firstk;
                    f0     = cap ? a0   : f0;
                    f1     = cap ? a1   : f1;
                    first_done |= diff;
                    a0 = diff ? v0 : (a0 + v0);
                    a1 = diff ? v1 : (a1 + v1);
                    curk = k;
                }
            }

            // boundary runs: atomics target addresses disjoint from ALL
            // interior RMWs this partition -> no barrier needed first.
            atomicAdd(&acc2[2 * curk],     a0);
            atomicAdd(&acc2[2 * curk + 1], a1);
            if (first_done) {
                atomicAdd(&acc2[2 * firstk],     f0);
                atomicAdd(&acc2[2 * firstk + 1], f1);
            }
        }

        // ---- convert + store staged rates into the other buffer ----
        if (have) {
            #pragma unroll
            for (int j = 0; j < STG_F2; ++j) {
                int f2 = j * MAIN_THREADS + tid;
                __half2 ha = __floats2half2_rn(s0v[j].x, s1v[j].x);
                __half2 hb = __floats2half2_rn(s0v[j].y, s1v[j].y);
                uint2 w; w.x = *(uint32_t*)&ha; w.y = *(uint32_t*)&hb;
                *(uint2*)(rnxt + 2 * f2) = w;            // STS.64
            }
        }

        __syncthreads();   // orders: STS rates, interior RMWs, atomics
    }

    // ---- write out both rows ----
    #pragma unroll
    for (int i = tid; i < S; i += MAIN_THREADS) {
        float2 t = *(const float2*)(acc2 + 2 * i);
        y_out[(size_t)b0 * S + i] = t.x;
        y_out[(size_t)b1 * S + i] = t.y;
    }
}

// ---------------- launch ----------------

extern "C" void kernel_launch(void* const* d_in, const int* in_sizes, int n_in,
                              void* d_out, int out_size) {
    const float* y_in      = (const float*)d_in[0];
    const float* rates_1st = (const float*)d_in[1];
    const float* rates_2nd = (const float*)d_in[2];
    const int*   inds_1r   = (const int*)d_in[3];
    const int*   inds_1p   = (const int*)d_in[4];
    const int*   inds_2r   = (const int*)d_in[5];
    const int*   inds_2p   = (const int*)d_in[6];
    float*       y_out     = (float*)d_out;

    cudaFuncSetAttribute(reaction_main_kernel,
                         cudaFuncAttributeMaxDynamicSharedMemorySize,
                         SMEM_BYTES);

    // Entry-stream build (rebuilt every launch; deterministic).
    hist_kernel<<<(RTOT + 255) / 256, 256>>>(inds_1p, inds_2p);
    scan_kernel<<<NPART, 1024>>>();
    scatter_pad_kernel<<<(NPART * RPP + 255) / 256, 256>>>(
        inds_1r, inds_1p, inds_2r, inds_2p);

    // Main pass: one CTA per TWO batch rows, staged/swept in a 12-stage pipeline
    reaction_main_kernel<<<NPAIR, MAIN_THREADS, SMEM_BYTES>>>(
        y_in, rates_1st, rates_2nd, y_out);
}